// round 14
// baseline (speedup 1.0000x reference)
#include <cuda_runtime.h>
#include <math.h>
#include <stdint.h>

#define Bn 8
#define C 128
#define HW 16384
#define Ncls 16
#define EPSF 1e-7f
#define NQ 39
#define KS 32
#define KPC (HW/KS)   // 512 pixels per gram CTA

// ---------------- tf32 mma.sync helpers (baseline PTX, sm_80+) ----------------
__device__ __forceinline__ uint32_t f2tf32(float v) {
    uint32_t r; asm("cvt.rna.tf32.f32 %0, %1;" : "=r"(r) : "f"(v)); return r;
}
#define MMA_TF32(d, a0,a1,a2,a3, b0,b1) \
    asm volatile("mma.sync.aligned.m16n8k8.row.col.f32.tf32.tf32.f32 " \
        "{%0,%1,%2,%3}, {%4,%5,%6,%7}, {%8,%9}, {%0,%1,%2,%3};" \
        : "+f"((d)[0]), "+f"((d)[1]), "+f"((d)[2]), "+f"((d)[3]) \
        : "r"(a0), "r"(a1), "r"(a2), "r"(a3), "r"(b0), "r"(b1))

// ---------------- scratch ----------------
__device__ float g_G[Bn*C*C];
__device__ float g_sx[Bn*C];
__device__ float g_H[Bn*3*C*C];
__device__ float g_A[Bn*C];          // sigma * A  (per-batch row scale)
__device__ float g_d[Bn*C];
__device__ float g_red[Bn*NQ*C];
__device__ float g_u[C];
__device__ uint32_t g_Wo32[C*C];     // Wo pre-rounded to tf32 bits (batch-invariant)

// ---------------- setup: zero scratch + u + Wo32 + orthogonality loss ----------------
__global__ void setup_kernel(const float* __restrict__ Wsa, const float* __restrict__ Wo,
                             const float* __restrict__ kn, float* __restrict__ out,
                             int out_size) {
    int i = blockIdx.x * blockDim.x + threadIdx.x;
    if (i < Bn*C*C)  g_G[i] = 0.f;
    if (i < Bn*C)    { g_sx[i] = 0.f; g_A[i] = 0.f; g_d[i] = 0.f; }
    if (i < Bn*NQ*C) g_red[i] = 0.f;
    if (i < C*C)     g_Wo32[i] = f2tf32(Wo[i]);
    if (blockIdx.x == 0 && threadIdx.x < C) {
        float u = 0.f;
        #pragma unroll 4
        for (int r = 0; r < C; r++) u += Wsa[r*C + threadIdx.x];
        g_u[threadIdx.x] = u;
    }
    if (blockIdx.x == 1) {
        __shared__ float sym[Ncls][Ncls];
        __shared__ float partial[256];
        int tid = threadIdx.x;
        int ii = tid >> 4, jj = tid & 15;
        float dot = 0.f;
        #pragma unroll 4
        for (int k = 0; k < C; k++) dot = fmaf(kn[ii*C + k], kn[jj*C + k], dot);
        sym[ii][jj] = dot;
        __syncthreads();
        float nr = sqrtf(sym[ii][ii]) * sqrtf(sym[jj][jj]);
        float l = sym[ii][jj] / (nr + EPSF) - (ii == jj ? 1.f : 0.f);
        partial[tid] = l * l;
        __syncthreads();
        for (int s = 128; s > 0; s >>= 1) {
            if (tid < s) partial[tid] += partial[tid + s];
            __syncthreads();
        }
        if (tid == 0) {
            float loss = 0.1f * logf(partial[0] + 1.f);
            for (int idx = Bn*C*HW; idx < out_size; idx++) out[idx] = loss;
        }
    }
}

// ---------------- Gram via mma.sync tf32: G[b] += X X^T ----------------
// Double-buffered 32-pixel tiles, ONE barrier per tile. Raw fp32 bits to tf32
// MMA (HW truncation). 2D warp blocking: 8 warps as 2x4; warp = 4 m16 x 4 n8.
__global__ __launch_bounds__(256, 2) void gram_mma_kernel(const float* __restrict__ x) {
    const int ks = blockIdx.x;
    const int b  = blockIdx.y;
    const int tid = threadIdx.x;
    const int w = tid >> 5, lane = tid & 31;
    const int gid = lane >> 2, tig = lane & 3;
    const int wm = w >> 2, wn = w & 3;   // warp grid 2x4

    __shared__ uint32_t xt[2][C*36];   // [buf][c*36 + p], 32 pixels per buffer

    float acc[4][4][4];   // [mt][t4][frag]
    #pragma unroll
    for (int mt = 0; mt < 4; mt++)
        #pragma unroll
        for (int t4 = 0; t4 < 4; t4++) {
            acc[mt][t4][0]=0.f; acc[mt][t4][1]=0.f; acc[mt][t4][2]=0.f; acc[mt][t4][3]=0.f;
        }

    const int c   = tid >> 1;
    const int seg = tid & 1;           // 16 pixels each
    const float* xp = x + ((size_t)b*C + c)*HW + ks*KPC + seg*16;
    float ssum = 0.f;

    float4 v[4];
    #pragma unroll
    for (int j = 0; j < 4; j++) v[j] = *reinterpret_cast<const float4*>(xp + j*4);

    const int NT = KPC/32;   // 16 tiles
    for (int t = 0; t < NT; t++) {
        uint32_t* buf = xt[t & 1];
        #pragma unroll
        for (int j = 0; j < 4; j++) {
            ssum += (v[j].x + v[j].y) + (v[j].z + v[j].w);
            *reinterpret_cast<float4*>(&buf[c*36 + seg*16 + j*4]) = v[j];   // raw fp32 bits
        }
        __syncthreads();
        if (t + 1 < NT) {
            const float* np = xp + (size_t)(t + 1)*32;
            #pragma unroll
            for (int j = 0; j < 4; j++) v[j] = *reinterpret_cast<const float4*>(np + j*4);
        }
        #pragma unroll
        for (int k8 = 0; k8 < 4; k8++) {
            const int kc = k8*8 + tig;
            uint32_t b0[4], b1[4];
            #pragma unroll
            for (int t4 = 0; t4 < 4; t4++) {
                const int col8 = (wn*4 + t4)*8 + gid;
                b0[t4] = buf[col8*36 + kc];
                b1[t4] = buf[col8*36 + kc + 4];
            }
            #pragma unroll
            for (int mt = 0; mt < 4; mt++) {
                const int r = (wm*4 + mt)*16 + gid;
                uint32_t a0 = buf[ r     *36 + kc];
                uint32_t a1 = buf[(r + 8)*36 + kc];
                uint32_t a2 = buf[ r     *36 + kc + 4];
                uint32_t a3 = buf[(r + 8)*36 + kc + 4];
                #pragma unroll
                for (int t4 = 0; t4 < 4; t4++)
                    MMA_TF32(acc[mt][t4], a0, a1, a2, a3, b0[t4], b1[t4]);
            }
        }
    }

    float* Gb = g_G + b*C*C;
    #pragma unroll
    for (int mt = 0; mt < 4; mt++) {
        const int row0 = (wm*4 + mt)*16 + gid;
        #pragma unroll
        for (int t4 = 0; t4 < 4; t4++) {
            const int col0 = (wn*4 + t4)*8 + 2*tig;
            atomicAdd(&Gb[ row0   *C + col0    ], acc[mt][t4][0]);
            atomicAdd(&Gb[ row0   *C + col0 + 1], acc[mt][t4][1]);
            atomicAdd(&Gb[(row0+8)*C + col0    ], acc[mt][t4][2]);
            atomicAdd(&Gb[(row0+8)*C + col0 + 1], acc[mt][t4][3]);
        }
    }
    atomicAdd(&g_sx[b*C + c], ssum);
}

// ---------------- H_m[b] = G[b] @ W_m^T  (row-split x2) ----------------
__global__ __launch_bounds__(256) void hgemm_kernel(const float* __restrict__ Wr,
                                                    const float* __restrict__ Wsa,
                                                    const float* __restrict__ Wo) {
    const int m    = blockIdx.x >> 1;
    const int half = blockIdx.x & 1;
    const int b = blockIdx.y;
    const float* W = (m == 0) ? Wr : (m == 1) ? Wsa : Wo;
    const float* G = g_G + b * C * C + half * 64 * C;
    float* H = g_H + (b * 3 + m) * C * C + half * 64 * C;

    __shared__ float As[64][33];
    __shared__ float Bs[C][33];
    const int tid = threadIdx.x;
    const int tx = tid & 15, ty = tid >> 4;
    const int kk = tid & 31, r0w = tid >> 5;

    float accA[4][4] = {}, accB[4][4] = {};

    for (int k0 = 0; k0 < C; k0 += 32) {
        #pragma unroll
        for (int i = 0; i < 8; i++) {
            int r = r0w + i * 8;
            As[r][kk] = G[r*C + k0 + kk];
        }
        #pragma unroll
        for (int i = 0; i < 16; i++) {
            int r = r0w + i * 8;
            Bs[r][kk] = W[r*C + k0 + kk];
        }
        __syncthreads();
        #pragma unroll 4
        for (int k = 0; k < 32; k++) {
            float a0[4], b0[4], b1[4];
            #pragma unroll
            for (int i = 0; i < 4; i++) a0[i] = As[ty*4+i][k];
            #pragma unroll
            for (int j = 0; j < 4; j++) { b0[j] = Bs[tx*4+j][k]; b1[j] = Bs[64+tx*4+j][k]; }
            #pragma unroll
            for (int i = 0; i < 4; i++)
                #pragma unroll
                for (int j = 0; j < 4; j++) {
                    accA[i][j] = fmaf(a0[i], b0[j], accA[i][j]);
                    accB[i][j] = fmaf(a0[i], b1[j], accB[i][j]);
                }
        }
        __syncthreads();
    }

    #pragma unroll
    for (int i = 0; i < 4; i++) {
        int r0 = ty*4 + i;
        #pragma unroll
        for (int j = 0; j < 4; j++) {
            H[r0*C + tx*4 + j]      = accA[i][j];
            H[r0*C + 64 + tx*4 + j] = accB[i][j];
        }
    }
}

// ---------------- reduce: 39 per-(b,c) reductions over i, split 16 ways ----------------
__global__ __launch_bounds__(128) void reduce_kernel(
    const float* __restrict__ Wr, const float* __restrict__ Wsa,
    const float* __restrict__ Wo, const float* __restrict__ kn)
{
    const int b   = blockIdx.x;
    const int i0  = blockIdx.y * 8;
    const int c   = threadIdx.x;
    const float* G  = g_G + b*C*C;
    const float* Hr = g_H + (b*3 + 0)*C*C;
    const float* Hs = g_H + (b*3 + 1)*C*C;
    const float* Ho = g_H + (b*3 + 2)*C*C;

    __shared__ float kn_s[8][Ncls];
    __shared__ float s_s[8], u_s[8];
    {
        int t = threadIdx.x;
        int n = t & 15, ii = t >> 4;
        kn_s[ii][n] = kn[n*C + i0 + ii];
        if (t < 8) { s_s[t] = g_sx[b*C + i0 + t]; u_s[t] = g_u[i0 + t]; }
    }
    __syncthreads();

    float nxr2 = 0.f, dsa = 0.f, s2v = 0.f, csum = 0.f;
    float wr_s = 0.f, wsa_s = 0.f, wo_s = 0.f;
    float rel[Ncls], P[Ncls];
    #pragma unroll
    for (int n = 0; n < Ncls; n++) { rel[n] = 0.f; P[n] = 0.f; }

    #pragma unroll
    for (int ii = 0; ii < 8; ii++) {
        const int i = i0 + ii;
        float hr = Hr[i*C + c];
        float hs = Hs[i*C + c];
        float ho = Ho[i*C + c];
        float g  = G [i*C + c];
        float wri = Wr[c*C + i], wsi = Wsa[c*C + i], woi = Wo[c*C + i];
        float si = s_s[ii], ui = u_s[ii];
        nxr2 = fmaf(wri, hr, nxr2);
        dsa  = fmaf(wsi, hs, dsa);
        s2v  = fmaf(woi, ho, s2v);
        csum = fmaf(ui,  hs, csum);
        wr_s = fmaf(wri, si, wr_s);
        wsa_s= fmaf(wsi, si, wsa_s);
        wo_s = fmaf(woi, si, wo_s);
        #pragma unroll
        for (int n = 0; n < Ncls; n++) {
            float kv = kn_s[ii][n];
            rel[n] = fmaf(kv, hr, rel[n]);
            P[n]   = fmaf(kv, g,  P[n]);
        }
    }

    float* R = g_red + b*NQ*C;
    atomicAdd(&R[0*C + c], nxr2);
    atomicAdd(&R[1*C + c], dsa);
    atomicAdd(&R[2*C + c], s2v);
    atomicAdd(&R[3*C + c], csum);
    atomicAdd(&R[4*C + c], wr_s);
    atomicAdd(&R[5*C + c], wsa_s);
    atomicAdd(&R[6*C + c], wo_s);
    #pragma unroll
    for (int n = 0; n < Ncls; n++) {
        atomicAdd(&R[(7 + n)*C + c],  rel[n]);
        atomicAdd(&R[(23 + n)*C + c], P[n]);
    }
}

// ---------------- finalize ----------------
__global__ __launch_bounds__(128) void finalize_kernel(
    const float* __restrict__ bsa, const float* __restrict__ br,
    const float* __restrict__ kn,  const float* __restrict__ bo,
    const float* __restrict__ alpha, const float* __restrict__ sigma)
{
    const int b = blockIdx.x;
    const int c = threadIdx.x;
    const float* R = g_red + b*NQ*C;
    const float hwf = 16384.f;

    __shared__ float s_sh[C], m_sh[C], s1_sh[C], s2_sh[C], red_s[C];
    __shared__ float att_sh[Ncls][C];
    __shared__ float pn_sh[Ncls][C];
    __shared__ float nxn_sh[Ncls], kns_sh[Ncls], inv_sh[Ncls], minv_sh[Ncls];
    __shared__ float sc_us, sc_sb, sc_mx, sc_sum;

    float s_c = g_sx[b*C + c];
    s_sh[c] = s_c;
    float u_c = g_u[c];
    float bsc = bsa[c], brc = br[c], boc = bo[c];

    red_s[c] = u_c * s_c;
    __syncthreads();
    #pragma unroll
    for (int s = 64; s > 0; s >>= 1) { if (c < s) red_s[c] += red_s[c + s]; __syncthreads(); }
    if (c == 0) sc_us = red_s[0];
    __syncthreads();
    red_s[c] = bsc;
    __syncthreads();
    #pragma unroll
    for (int s = 64; s > 0; s >>= 1) { if (c < s) red_s[c] += red_s[c + s]; __syncthreads(); }
    if (c == 0) sc_sb = red_s[0];
    __syncthreads();

    #pragma unroll
    for (int n = 0; n < Ncls; n++) pn_sh[n][c] = R[(23 + n)*C + c] * kn[n*C + c];
    __syncthreads();
    if (c < Ncls) {
        float t = 0.f;
        #pragma unroll 4
        for (int k = 0; k < C; k++) t += pn_sh[c][k];
        nxn_sh[c] = sqrtf(t);
    }
    __syncthreads();
    #pragma unroll
    for (int n = 0; n < Ncls; n++) pn_sh[n][c] = kn[n*C + c] * s_sh[c];
    __syncthreads();
    if (c < Ncls) {
        float t = 0.f;
        #pragma unroll 4
        for (int k = 0; k < C; k++) t += pn_sh[c][k];
        kns_sh[c] = t;
    }
    __syncthreads();

    float wr_s = R[4*C + c], wsa_s = R[5*C + c], wo_s = R[6*C + c];
    float nxr2 = R[0*C + c] + 2.f*brc*wr_s + hwf*brc*brc;
    float nxr  = sqrtf(nxr2);
    float dsa  = R[1*C + c] + 2.f*bsc*wsa_s + hwf*bsc*bsc;
    float csum = R[3*C + c] + sc_sb*wsa_s + bsc*sc_us + hwf*sc_sb*bsc;
    m_sh[c]  = (csum - dsa) * (1.f/128.f);
    s1_sh[c] = wo_s + hwf*boc;
    s2_sh[c] = R[2*C + c] + 2.f*boc*wo_s + hwf*boc*boc;
    __syncthreads();

    red_s[c] = m_sh[c];
    __syncthreads();
    #pragma unroll
    for (int s = 64; s > 0; s >>= 1) { if (c < s) red_s[c] = fmaxf(red_s[c], red_s[c + s]); __syncthreads(); }
    if (c == 0) sc_mx = red_s[0];
    __syncthreads();
    float ex = expf(m_sh[c] - sc_mx);
    red_s[c] = ex;
    __syncthreads();
    #pragma unroll
    for (int s = 64; s > 0; s >>= 1) { if (c < s) red_s[c] += red_s[c + s]; __syncthreads(); }
    if (c == 0) sc_sum = red_s[0];
    __syncthreads();
    float regular = ex / sc_sum;

    {
        float rn[Ncls];
        float mxn = -1e30f;
        #pragma unroll
        for (int n = 0; n < Ncls; n++) {
            float r = R[(7 + n)*C + c] + brc * kns_sh[n];
            float al = fminf(fmaxf(alpha[n], 0.f), 1.f);
            rn[n] = r / (nxn_sh[n]*nxr + EPSF) + al * regular;
            mxn = fmaxf(mxn, rn[n]);
        }
        float se = 0.f;
        #pragma unroll
        for (int n = 0; n < Ncls; n++) { rn[n] = expf(rn[n] - mxn); se += rn[n]; }
        float ise = 1.f / se;
        #pragma unroll
        for (int n = 0; n < Ncls; n++) att_sh[n][c] = rn[n] * ise;
    }
    __syncthreads();

    if (c < Ncls) {
        int n = c;
        float cnt = 0.f, hot = 0.f, sq2 = 0.f;
        #pragma unroll 4
        for (int cc = 0; cc < C; cc++) {
            float a = att_sh[n][cc];
            cnt += a;
            hot = fmaf(a, s1_sh[cc], hot);
            sq2 = fmaf(a*a, s2_sh[cc], sq2);
        }
        cnt = cnt * hwf + EPSF;
        float mean = hot / cnt;
        float sq = sq2 - 2.f*mean*hot + mean*mean*(128.f*hwf);
        float stdv = sqrtf(sq / cnt);
        float inv = 1.f / (stdv + EPSF);
        inv_sh[n] = inv; minv_sh[n] = mean * inv;
    }
    __syncthreads();

    float sg = sigma[0];
    {
        float Av = 0.f, Bv = 0.f;
        #pragma unroll
        for (int n = 0; n < Ncls; n++) {
            float a = att_sh[n][c];
            Av = fmaf(a, inv_sh[n],  Av);
            Bv = fmaf(a, minv_sh[n], Bv);
        }
        g_A[b*C + c] = sg * Av;
        g_d[b*C + c] = sg * (Av * boc - Bv);
    }
}

// ---------------- out = x + sA[r]*(Wo_hi@(x_hi+x_lo)) + d  (2-pass tf32) ----------------
// Double-buffered, ONE barrier per chunk; x split by mantissa mask (exact).
// grid (HW/128, Bn), block 256.
__global__ __launch_bounds__(256) void out_mma_kernel(const float* __restrict__ x,
                                                      float* __restrict__ out) {
    const int p0 = blockIdx.x * 128;
    const int b  = blockIdx.y;
    const int tid = threadIdx.x;
    const int w = tid >> 5, lane = tid & 31;
    const int gid = lane >> 2, tig = lane & 3;

    __shared__ uint32_t a_hi[2][C*20];       // [buf][row*20 + k] (Wo chunk, tf32 bits)
    __shared__ uint32_t xs_hi[2][16*136];    // [buf][k*136 + p]
    __shared__ uint32_t xs_lo[2][16*136];
    __shared__ float dsm[C], asm_[C];

    const uint32_t* Mb = g_Wo32;
    const float* xb = x + (size_t)b*C*HW;

    if (tid < C) { dsm[tid] = g_d[b*C + tid]; asm_[tid] = g_A[b*C + tid]; }

    float acc[8][2][4];
    #pragma unroll
    for (int mt = 0; mt < 8; mt++)
        #pragma unroll
        for (int nt = 0; nt < 2; nt++) {
            acc[mt][nt][0]=0.f; acc[mt][nt][1]=0.f; acc[mt][nt][2]=0.f; acc[mt][nt][3]=0.f;
        }

    const int mc = tid >> 1, mseg = tid & 1;
    const int xk = tid >> 4, xsg = tid & 15;

    uint4 vm[2]; float4 vx[2];
    #pragma unroll
    for (int j = 0; j < 2; j++) {
        vm[j] = *reinterpret_cast<const uint4*>(Mb + mc*C + mseg*8 + j*4);
        vx[j] = *reinterpret_cast<const float4*>(xb + (size_t)xk*HW + p0 + xsg*8 + j*4);
    }

    const uint32_t MSK = 0xFFFFE000u;   // keep tf32 mantissa bits (exact split)
    for (int ch = 0; ch < 8; ch++) {
        const int s = ch & 1;
        #pragma unroll
        for (int j = 0; j < 2; j++)
            *reinterpret_cast<uint4*>(&a_hi[s][mc*20 + mseg*8 + j*4]) = vm[j];
        #pragma unroll
        for (int j = 0; j < 2; j++) {
            uint4 h, l;
            h.x = __float_as_uint(vx[j].x) & MSK; l.x = __float_as_uint(vx[j].x - __uint_as_float(h.x));
            h.y = __float_as_uint(vx[j].y) & MSK; l.y = __float_as_uint(vx[j].y - __uint_as_float(h.y));
            h.z = __float_as_uint(vx[j].z) & MSK; l.z = __float_as_uint(vx[j].z - __uint_as_float(h.z));
            h.w = __float_as_uint(vx[j].w) & MSK; l.w = __float_as_uint(vx[j].w - __uint_as_float(h.w));
            *reinterpret_cast<uint4*>(&xs_hi[s][xk*136 + xsg*8 + j*4]) = h;
            *reinterpret_cast<uint4*>(&xs_lo[s][xk*136 + xsg*8 + j*4]) = l;
        }
        __syncthreads();   // single barrier: MMA(ch) overlaps STS(ch+1) across warps
        if (ch + 1 < 8) {
            const int k0n = (ch + 1)*16;
            #pragma unroll
            for (int j = 0; j < 2; j++) {
                vm[j] = *reinterpret_cast<const uint4*>(Mb + mc*C + k0n + mseg*8 + j*4);
                vx[j] = *reinterpret_cast<const float4*>(xb + (size_t)(k0n + xk)*HW + p0 + xsg*8 + j*4);
            }
        }
        #pragma unroll
        for (int k8 = 0; k8 < 2; k8++) {
            const int kc = k8*8 + tig;
            uint32_t Bf[2][4];
            #pragma unroll
            for (int nt = 0; nt < 2; nt++) {
                const int col = w*16 + nt*8 + gid;
                Bf[nt][0] = xs_hi[s][ kc   *136 + col];
                Bf[nt][1] = xs_hi[s][(kc+4)*136 + col];
                Bf[nt][2] = xs_lo[s][ kc   *136 + col];
                Bf[nt][3] = xs_lo[s][(kc+4)*136 + col];
            }
            #pragma unroll
            for (int mt = 0; mt < 8; mt++) {
                uint32_t a0 = a_hi[s][(mt*16 + gid    )*20 + kc];
                uint32_t a1 = a_hi[s][(mt*16 + gid + 8)*20 + kc];
                uint32_t a2 = a_hi[s][(mt*16 + gid    )*20 + kc + 4];
                uint32_t a3 = a_hi[s][(mt*16 + gid + 8)*20 + kc + 4];
                #pragma unroll
                for (int nt = 0; nt < 2; nt++) {
                    MMA_TF32(acc[mt][nt], a0, a1, a2, a3, Bf[nt][0], Bf[nt][1]);
                    MMA_TF32(acc[mt][nt], a0, a1, a2, a3, Bf[nt][2], Bf[nt][3]);
                }
            }
        }
    }

    // direct epilogue: out[r][p] = x[r][p] + sA[r]*delta + d[r]
    float* ob = out + (size_t)b*C*HW;
    #pragma unroll
    for (int mt = 0; mt < 8; mt++) {
        const int r0 = mt*16 + gid, r1 = r0 + 8;
        const float d0 = dsm[r0], d1 = dsm[r1];
        const float a0 = asm_[r0], a1 = asm_[r1];
        #pragma unroll
        for (int nt = 0; nt < 2; nt++) {
            const int p = p0 + w*16 + nt*8 + 2*tig;
            float2 xv0 = *reinterpret_cast<const float2*>(xb + (size_t)r0*HW + p);
            float2 xv1 = *reinterpret_cast<const float2*>(xb + (size_t)r1*HW + p);
            float2 o0, o1;
            o0.x = fmaf(a0, acc[mt][nt][0], xv0.x + d0);
            o0.y = fmaf(a0, acc[mt][nt][1], xv0.y + d0);
            o1.x = fmaf(a1, acc[mt][nt][2], xv1.x + d1);
            o1.y = fmaf(a1, acc[mt][nt][3], xv1.y + d1);
            *reinterpret_cast<float2*>(ob + (size_t)r0*HW + p) = o0;
            *reinterpret_cast<float2*>(ob + (size_t)r1*HW + p) = o1;
        }
    }
}

extern "C" void kernel_launch(void* const* d_in, const int* in_sizes, int n_in,
                              void* d_out, int out_size) {
    const float* x     = (const float*)d_in[0];
    const float* Wsa   = (const float*)d_in[1];
    const float* bsa   = (const float*)d_in[2];
    const float* Wr    = (const float*)d_in[3];
    const float* br    = (const float*)d_in[4];
    const float* kn    = (const float*)d_in[5];
    const float* Wo    = (const float*)d_in[6];
    const float* bo    = (const float*)d_in[7];
    const float* alpha = (const float*)d_in[8];
    const float* sigma = (const float*)d_in[9];
    float* out = (float*)d_out;

    setup_kernel<<<(Bn*C*C + 255) / 256, 256>>>(Wsa, Wo, kn, out, out_size);  // 1
    gram_mma_kernel<<<dim3(KS, Bn), 256>>>(x);                                // 2
    hgemm_kernel<<<dim3(6, Bn), 256>>>(Wr, Wsa, Wo);                          // 3
    // PROBE: deterministic (g_A=g_d=0 from setup); output overwritten by the
    // real out_mma below. Exists solely so ncu (launch #4) profiles out_mma.
    out_mma_kernel<<<dim3(HW/128, Bn), 256>>>(x, out);                        // 4 -> profiled
    reduce_kernel<<<dim3(Bn, 16), 128>>>(Wr, Wsa, Wo, kn);                    // 5
    finalize_kernel<<<Bn, 128>>>(bsa, br, kn, bo, alpha, sigma);              // 6
    out_mma_kernel<<<dim3(HW/128, Bn), 256>>>(x, out);                        // 7 (real)
}

// round 15
// speedup vs baseline: 1.6039x; 1.6039x over previous
#include <cuda_runtime.h>
#include <math.h>
#include <stdint.h>

#define Bn 8
#define C 128
#define HW 16384
#define Ncls 16
#define EPSF 1e-7f
#define NQ 39
#define KS 32
#define KPC (HW/KS)   // 512 pixels per gram CTA

// ---------------- tf32 mma.sync helpers (baseline PTX, sm_80+) ----------------
__device__ __forceinline__ uint32_t f2tf32(float v) {
    uint32_t r; asm("cvt.rna.tf32.f32 %0, %1;" : "=r"(r) : "f"(v)); return r;
}
#define MMA_TF32(d, a0,a1,a2,a3, b0,b1) \
    asm volatile("mma.sync.aligned.m16n8k8.row.col.f32.tf32.tf32.f32 " \
        "{%0,%1,%2,%3}, {%4,%5,%6,%7}, {%8,%9}, {%0,%1,%2,%3};" \
        : "+f"((d)[0]), "+f"((d)[1]), "+f"((d)[2]), "+f"((d)[3]) \
        : "r"(a0), "r"(a1), "r"(a2), "r"(a3), "r"(b0), "r"(b1))

// ---------------- scratch ----------------
__device__ float g_G[Bn*C*C];
__device__ float g_sx[Bn*C];
__device__ float g_H[Bn*3*C*C];
__device__ float g_A[Bn*C];          // sigma * A  (per-batch row scale)
__device__ float g_d[Bn*C];
__device__ float g_red[Bn*NQ*C];
__device__ float g_u[C];
__device__ uint32_t g_Wo32[C*C];     // Wo pre-rounded to tf32 bits (batch-invariant)

// ---------------- setup: zero scratch + u + Wo32 + orthogonality loss ----------------
__global__ void setup_kernel(const float* __restrict__ Wsa, const float* __restrict__ Wo,
                             const float* __restrict__ kn, float* __restrict__ out,
                             int out_size) {
    int i = blockIdx.x * blockDim.x + threadIdx.x;
    if (i < Bn*C*C)  g_G[i] = 0.f;
    if (i < Bn*C)    g_sx[i] = 0.f;
    if (i < Bn*NQ*C) g_red[i] = 0.f;
    if (i < C*C)     g_Wo32[i] = f2tf32(Wo[i]);
    if (blockIdx.x == 0 && threadIdx.x < C) {
        float u = 0.f;
        #pragma unroll 4
        for (int r = 0; r < C; r++) u += Wsa[r*C + threadIdx.x];
        g_u[threadIdx.x] = u;
    }
    if (blockIdx.x == 1) {
        __shared__ float sym[Ncls][Ncls];
        __shared__ float partial[256];
        int tid = threadIdx.x;
        int ii = tid >> 4, jj = tid & 15;
        float dot = 0.f;
        #pragma unroll 4
        for (int k = 0; k < C; k++) dot = fmaf(kn[ii*C + k], kn[jj*C + k], dot);
        sym[ii][jj] = dot;
        __syncthreads();
        float nr = sqrtf(sym[ii][ii]) * sqrtf(sym[jj][jj]);
        float l = sym[ii][jj] / (nr + EPSF) - (ii == jj ? 1.f : 0.f);
        partial[tid] = l * l;
        __syncthreads();
        for (int s = 128; s > 0; s >>= 1) {
            if (tid < s) partial[tid] += partial[tid + s];
            __syncthreads();
        }
        if (tid == 0) {
            float loss = 0.1f * logf(partial[0] + 1.f);
            for (int idx = Bn*C*HW; idx < out_size; idx++) out[idx] = loss;
        }
    }
}

// ---------------- Gram via mma.sync tf32: G[b] += X X^T ----------------
// Double-buffered 32-pixel tiles, ONE barrier per tile; cvt.rna (unbiased).
// 2D warp blocking: 8 warps as 2x4; warp = 4 m16 x 4 n8.
__global__ __launch_bounds__(256, 2) void gram_mma_kernel(const float* __restrict__ x) {
    const int ks = blockIdx.x;
    const int b  = blockIdx.y;
    const int tid = threadIdx.x;
    const int w = tid >> 5, lane = tid & 31;
    const int gid = lane >> 2, tig = lane & 3;
    const int wm = w >> 2, wn = w & 3;   // warp grid 2x4

    __shared__ uint32_t xt[2][C*36];   // [buf][c*36 + p], 32 pixels per buffer

    float acc[4][4][4];   // [mt][t4][frag]
    #pragma unroll
    for (int mt = 0; mt < 4; mt++)
        #pragma unroll
        for (int t4 = 0; t4 < 4; t4++) {
            acc[mt][t4][0]=0.f; acc[mt][t4][1]=0.f; acc[mt][t4][2]=0.f; acc[mt][t4][3]=0.f;
        }

    const int c   = tid >> 1;
    const int seg = tid & 1;           // 16 pixels each
    const float* xp = x + ((size_t)b*C + c)*HW + ks*KPC + seg*16;
    float ssum = 0.f;

    float4 v[4];
    #pragma unroll
    for (int j = 0; j < 4; j++) v[j] = *reinterpret_cast<const float4*>(xp + j*4);

    const int NT = KPC/32;   // 16 tiles
    for (int t = 0; t < NT; t++) {
        uint32_t* buf = xt[t & 1];
        #pragma unroll
        for (int j = 0; j < 4; j++) {
            ssum += (v[j].x + v[j].y) + (v[j].z + v[j].w);
            uint4 u;
            u.x = f2tf32(v[j].x); u.y = f2tf32(v[j].y);
            u.z = f2tf32(v[j].z); u.w = f2tf32(v[j].w);
            *reinterpret_cast<uint4*>(&buf[c*36 + seg*16 + j*4]) = u;
        }
        __syncthreads();
        if (t + 1 < NT) {
            const float* np = xp + (size_t)(t + 1)*32;
            #pragma unroll
            for (int j = 0; j < 4; j++) v[j] = *reinterpret_cast<const float4*>(np + j*4);
        }
        #pragma unroll
        for (int k8 = 0; k8 < 4; k8++) {
            const int kc = k8*8 + tig;
            uint32_t b0[4], b1[4];
            #pragma unroll
            for (int t4 = 0; t4 < 4; t4++) {
                const int col8 = (wn*4 + t4)*8 + gid;
                b0[t4] = buf[col8*36 + kc];
                b1[t4] = buf[col8*36 + kc + 4];
            }
            #pragma unroll
            for (int mt = 0; mt < 4; mt++) {
                const int r = (wm*4 + mt)*16 + gid;
                uint32_t a0 = buf[ r     *36 + kc];
                uint32_t a1 = buf[(r + 8)*36 + kc];
                uint32_t a2 = buf[ r     *36 + kc + 4];
                uint32_t a3 = buf[(r + 8)*36 + kc + 4];
                #pragma unroll
                for (int t4 = 0; t4 < 4; t4++)
                    MMA_TF32(acc[mt][t4], a0, a1, a2, a3, b0[t4], b1[t4]);
            }
        }
    }

    float* Gb = g_G + b*C*C;
    #pragma unroll
    for (int mt = 0; mt < 4; mt++) {
        const int row0 = (wm*4 + mt)*16 + gid;
        #pragma unroll
        for (int t4 = 0; t4 < 4; t4++) {
            const int col0 = (wn*4 + t4)*8 + 2*tig;
            atomicAdd(&Gb[ row0   *C + col0    ], acc[mt][t4][0]);
            atomicAdd(&Gb[ row0   *C + col0 + 1], acc[mt][t4][1]);
            atomicAdd(&Gb[(row0+8)*C + col0    ], acc[mt][t4][2]);
            atomicAdd(&Gb[(row0+8)*C + col0 + 1], acc[mt][t4][3]);
        }
    }
    atomicAdd(&g_sx[b*C + c], ssum);
}

// ---------------- H_m[b] = G[b] @ W_m^T  (row-split x2) ----------------
__global__ __launch_bounds__(256) void hgemm_kernel(const float* __restrict__ Wr,
                                                    const float* __restrict__ Wsa,
                                                    const float* __restrict__ Wo) {
    const int m    = blockIdx.x >> 1;
    const int half = blockIdx.x & 1;
    const int b = blockIdx.y;
    const float* W = (m == 0) ? Wr : (m == 1) ? Wsa : Wo;
    const float* G = g_G + b * C * C + half * 64 * C;
    float* H = g_H + (b * 3 + m) * C * C + half * 64 * C;

    __shared__ float As[64][33];
    __shared__ float Bs[C][33];
    const int tid = threadIdx.x;
    const int tx = tid & 15, ty = tid >> 4;
    const int kk = tid & 31, r0w = tid >> 5;

    float accA[4][4] = {}, accB[4][4] = {};

    for (int k0 = 0; k0 < C; k0 += 32) {
        #pragma unroll
        for (int i = 0; i < 8; i++) {
            int r = r0w + i * 8;
            As[r][kk] = G[r*C + k0 + kk];
        }
        #pragma unroll
        for (int i = 0; i < 16; i++) {
            int r = r0w + i * 8;
            Bs[r][kk] = W[r*C + k0 + kk];
        }
        __syncthreads();
        #pragma unroll 4
        for (int k = 0; k < 32; k++) {
            float a0[4], b0[4], b1[4];
            #pragma unroll
            for (int i = 0; i < 4; i++) a0[i] = As[ty*4+i][k];
            #pragma unroll
            for (int j = 0; j < 4; j++) { b0[j] = Bs[tx*4+j][k]; b1[j] = Bs[64+tx*4+j][k]; }
            #pragma unroll
            for (int i = 0; i < 4; i++)
                #pragma unroll
                for (int j = 0; j < 4; j++) {
                    accA[i][j] = fmaf(a0[i], b0[j], accA[i][j]);
                    accB[i][j] = fmaf(a0[i], b1[j], accB[i][j]);
                }
        }
        __syncthreads();
    }

    #pragma unroll
    for (int i = 0; i < 4; i++) {
        int r0 = ty*4 + i;
        #pragma unroll
        for (int j = 0; j < 4; j++) {
            H[r0*C + tx*4 + j]      = accA[i][j];
            H[r0*C + 64 + tx*4 + j] = accB[i][j];
        }
    }
}

// ---------------- reduce: 39 per-(b,c) reductions over i, split 16 ways ----------------
__global__ __launch_bounds__(128) void reduce_kernel(
    const float* __restrict__ Wr, const float* __restrict__ Wsa,
    const float* __restrict__ Wo, const float* __restrict__ kn)
{
    const int b   = blockIdx.x;
    const int i0  = blockIdx.y * 8;
    const int c   = threadIdx.x;
    const float* G  = g_G + b*C*C;
    const float* Hr = g_H + (b*3 + 0)*C*C;
    const float* Hs = g_H + (b*3 + 1)*C*C;
    const float* Ho = g_H + (b*3 + 2)*C*C;

    __shared__ float kn_s[8][Ncls];
    __shared__ float s_s[8], u_s[8];
    {
        int t = threadIdx.x;
        int n = t & 15, ii = t >> 4;
        kn_s[ii][n] = kn[n*C + i0 + ii];
        if (t < 8) { s_s[t] = g_sx[b*C + i0 + t]; u_s[t] = g_u[i0 + t]; }
    }
    __syncthreads();

    float nxr2 = 0.f, dsa = 0.f, s2v = 0.f, csum = 0.f;
    float wr_s = 0.f, wsa_s = 0.f, wo_s = 0.f;
    float rel[Ncls], P[Ncls];
    #pragma unroll
    for (int n = 0; n < Ncls; n++) { rel[n] = 0.f; P[n] = 0.f; }

    #pragma unroll
    for (int ii = 0; ii < 8; ii++) {
        const int i = i0 + ii;
        float hr = Hr[i*C + c];
        float hs = Hs[i*C + c];
        float ho = Ho[i*C + c];
        float g  = G [i*C + c];
        float wri = Wr[c*C + i], wsi = Wsa[c*C + i], woi = Wo[c*C + i];
        float si = s_s[ii], ui = u_s[ii];
        nxr2 = fmaf(wri, hr, nxr2);
        dsa  = fmaf(wsi, hs, dsa);
        s2v  = fmaf(woi, ho, s2v);
        csum = fmaf(ui,  hs, csum);
        wr_s = fmaf(wri, si, wr_s);
        wsa_s= fmaf(wsi, si, wsa_s);
        wo_s = fmaf(woi, si, wo_s);
        #pragma unroll
        for (int n = 0; n < Ncls; n++) {
            float kv = kn_s[ii][n];
            rel[n] = fmaf(kv, hr, rel[n]);
            P[n]   = fmaf(kv, g,  P[n]);
        }
    }

    float* R = g_red + b*NQ*C;
    atomicAdd(&R[0*C + c], nxr2);
    atomicAdd(&R[1*C + c], dsa);
    atomicAdd(&R[2*C + c], s2v);
    atomicAdd(&R[3*C + c], csum);
    atomicAdd(&R[4*C + c], wr_s);
    atomicAdd(&R[5*C + c], wsa_s);
    atomicAdd(&R[6*C + c], wo_s);
    #pragma unroll
    for (int n = 0; n < Ncls; n++) {
        atomicAdd(&R[(7 + n)*C + c],  rel[n]);
        atomicAdd(&R[(23 + n)*C + c], P[n]);
    }
}

// ---------------- finalize ----------------
__global__ __launch_bounds__(128) void finalize_kernel(
    const float* __restrict__ bsa, const float* __restrict__ br,
    const float* __restrict__ kn,  const float* __restrict__ bo,
    const float* __restrict__ alpha, const float* __restrict__ sigma)
{
    const int b = blockIdx.x;
    const int c = threadIdx.x;
    const float* R = g_red + b*NQ*C;
    const float hwf = 16384.f;

    __shared__ float s_sh[C], m_sh[C], s1_sh[C], s2_sh[C], red_s[C];
    __shared__ float att_sh[Ncls][C];
    __shared__ float pn_sh[Ncls][C];
    __shared__ float nxn_sh[Ncls], kns_sh[Ncls], inv_sh[Ncls], minv_sh[Ncls];
    __shared__ float sc_us, sc_sb, sc_mx, sc_sum;

    float s_c = g_sx[b*C + c];
    s_sh[c] = s_c;
    float u_c = g_u[c];
    float bsc = bsa[c], brc = br[c], boc = bo[c];

    red_s[c] = u_c * s_c;
    __syncthreads();
    #pragma unroll
    for (int s = 64; s > 0; s >>= 1) { if (c < s) red_s[c] += red_s[c + s]; __syncthreads(); }
    if (c == 0) sc_us = red_s[0];
    __syncthreads();
    red_s[c] = bsc;
    __syncthreads();
    #pragma unroll
    for (int s = 64; s > 0; s >>= 1) { if (c < s) red_s[c] += red_s[c + s]; __syncthreads(); }
    if (c == 0) sc_sb = red_s[0];
    __syncthreads();

    #pragma unroll
    for (int n = 0; n < Ncls; n++) pn_sh[n][c] = R[(23 + n)*C + c] * kn[n*C + c];
    __syncthreads();
    if (c < Ncls) {
        float t = 0.f;
        #pragma unroll 4
        for (int k = 0; k < C; k++) t += pn_sh[c][k];
        nxn_sh[c] = sqrtf(t);
    }
    __syncthreads();
    #pragma unroll
    for (int n = 0; n < Ncls; n++) pn_sh[n][c] = kn[n*C + c] * s_sh[c];
    __syncthreads();
    if (c < Ncls) {
        float t = 0.f;
        #pragma unroll 4
        for (int k = 0; k < C; k++) t += pn_sh[c][k];
        kns_sh[c] = t;
    }
    __syncthreads();

    float wr_s = R[4*C + c], wsa_s = R[5*C + c], wo_s = R[6*C + c];
    float nxr2 = R[0*C + c] + 2.f*brc*wr_s + hwf*brc*brc;
    float nxr  = sqrtf(nxr2);
    float dsa  = R[1*C + c] + 2.f*bsc*wsa_s + hwf*bsc*bsc;
    float csum = R[3*C + c] + sc_sb*wsa_s + bsc*sc_us + hwf*sc_sb*bsc;
    m_sh[c]  = (csum - dsa) * (1.f/128.f);
    s1_sh[c] = wo_s + hwf*boc;
    s2_sh[c] = R[2*C + c] + 2.f*boc*wo_s + hwf*boc*boc;
    __syncthreads();

    red_s[c] = m_sh[c];
    __syncthreads();
    #pragma unroll
    for (int s = 64; s > 0; s >>= 1) { if (c < s) red_s[c] = fmaxf(red_s[c], red_s[c + s]); __syncthreads(); }
    if (c == 0) sc_mx = red_s[0];
    __syncthreads();
    float ex = expf(m_sh[c] - sc_mx);
    red_s[c] = ex;
    __syncthreads();
    #pragma unroll
    for (int s = 64; s > 0; s >>= 1) { if (c < s) red_s[c] += red_s[c + s]; __syncthreads(); }
    if (c == 0) sc_sum = red_s[0];
    __syncthreads();
    float regular = ex / sc_sum;

    {
        float rn[Ncls];
        float mxn = -1e30f;
        #pragma unroll
        for (int n = 0; n < Ncls; n++) {
            float r = R[(7 + n)*C + c] + brc * kns_sh[n];
            float al = fminf(fmaxf(alpha[n], 0.f), 1.f);
            rn[n] = r / (nxn_sh[n]*nxr + EPSF) + al * regular;
            mxn = fmaxf(mxn, rn[n]);
        }
        float se = 0.f;
        #pragma unroll
        for (int n = 0; n < Ncls; n++) { rn[n] = expf(rn[n] - mxn); se += rn[n]; }
        float ise = 1.f / se;
        #pragma unroll
        for (int n = 0; n < Ncls; n++) att_sh[n][c] = rn[n] * ise;
    }
    __syncthreads();

    if (c < Ncls) {
        int n = c;
        float cnt = 0.f, hot = 0.f, sq2 = 0.f;
        #pragma unroll 4
        for (int cc = 0; cc < C; cc++) {
            float a = att_sh[n][cc];
            cnt += a;
            hot = fmaf(a, s1_sh[cc], hot);
            sq2 = fmaf(a*a, s2_sh[cc], sq2);
        }
        cnt = cnt * hwf + EPSF;
        float mean = hot / cnt;
        float sq = sq2 - 2.f*mean*hot + mean*mean*(128.f*hwf);
        float stdv = sqrtf(sq / cnt);
        float inv = 1.f / (stdv + EPSF);
        inv_sh[n] = inv; minv_sh[n] = mean * inv;
    }
    __syncthreads();

    float sg = sigma[0];
    {
        float Av = 0.f, Bv = 0.f;
        #pragma unroll
        for (int n = 0; n < Ncls; n++) {
            float a = att_sh[n][c];
            Av = fmaf(a, inv_sh[n],  Av);
            Bv = fmaf(a, minv_sh[n], Bv);
        }
        g_A[b*C + c] = sg * Av;
        g_d[b*C + c] = sg * (Av * boc - Bv);
    }
}

// ---------------- out = x + sA[r]*(Wo_hi @ x_rna) + d  (single-pass tf32) ----------------
// B fragments loaded DIRECTLY from gmem (4x32B full sectors per LDG); whole Wo
// resident in smem (pitch 132, conflict-free); no barriers in mainloop.
// grid (HW/128, Bn), block 256.
__global__ __launch_bounds__(256) void out_mma_kernel(const float* __restrict__ x,
                                                      float* __restrict__ out) {
    const int p0 = blockIdx.x * 128;
    const int b  = blockIdx.y;
    const int tid = threadIdx.x;
    const int w = tid >> 5, lane = tid & 31;
    const int gid = lane >> 2, tig = lane & 3;

    __shared__ uint32_t aW[C*132];     // full Wo, tf32 bits, padded pitch
    __shared__ float dsm[C], asm_[C];

    const float* xb = x + (size_t)b*C*HW;

    // load Wo32 into padded smem (once)
    #pragma unroll
    for (int it = 0; it < 16; it++) {
        int i = tid + it*256;                    // uint4 index (4096 total)
        int row = i >> 5, col = (i & 31) << 2;
        uint4 v = *reinterpret_cast<const uint4*>(g_Wo32 + row*C + col);
        *reinterpret_cast<uint4*>(&aW[row*132 + col]) = v;
    }
    if (tid < C) { dsm[tid] = g_d[b*C + tid]; asm_[tid] = g_A[b*C + tid]; }

    float acc[8][2][4];
    #pragma unroll
    for (int mt = 0; mt < 8; mt++)
        #pragma unroll
        for (int nt = 0; nt < 2; nt++) {
            acc[mt][nt][0]=0.f; acc[mt][nt][1]=0.f; acc[mt][nt][2]=0.f; acc[mt][nt][3]=0.f;
        }

    const int colb = p0 + w*16 + gid;

    // preload chunk-0 B fragments (tf32-rounded, unbiased rna)
    uint32_t rb[2][2][2];
    #pragma unroll
    for (int k8 = 0; k8 < 2; k8++)
        #pragma unroll
        for (int nt = 0; nt < 2; nt++) {
            rb[k8][nt][0] = f2tf32(xb[(size_t)(k8*8 + tig    )*HW + colb + nt*8]);
            rb[k8][nt][1] = f2tf32(xb[(size_t)(k8*8 + tig + 4)*HW + colb + nt*8]);
        }
    __syncthreads();   // aW/dsm/asm_ ready; only barrier in the kernel body

    for (int ch = 0; ch < 8; ch++) {
        uint32_t bf[2][2][2];
        #pragma unroll
        for (int k8 = 0; k8 < 2; k8++)
            #pragma unroll
            for (int nt = 0; nt < 2; nt++) {
                bf[k8][nt][0] = rb[k8][nt][0];
                bf[k8][nt][1] = rb[k8][nt][1];
            }
        if (ch + 1 < 8) {
            const int kr = (ch + 1)*16;
            #pragma unroll
            for (int k8 = 0; k8 < 2; k8++)
                #pragma unroll
                for (int nt = 0; nt < 2; nt++) {
                    rb[k8][nt][0] = f2tf32(xb[(size_t)(kr + k8*8 + tig    )*HW + colb + nt*8]);
                    rb[k8][nt][1] = f2tf32(xb[(size_t)(kr + k8*8 + tig + 4)*HW + colb + nt*8]);
                }
        }
        #pragma unroll
        for (int k8 = 0; k8 < 2; k8++) {
            const int kc = ch*16 + k8*8 + tig;
            #pragma unroll
            for (int mt = 0; mt < 8; mt++) {
                uint32_t a0 = aW[(mt*16 + gid    )*132 + kc];
                uint32_t a1 = aW[(mt*16 + gid + 8)*132 + kc];
                uint32_t a2 = aW[(mt*16 + gid    )*132 + kc + 4];
                uint32_t a3 = aW[(mt*16 + gid + 8)*132 + kc + 4];
                #pragma unroll
                for (int nt = 0; nt < 2; nt++)
                    MMA_TF32(acc[mt][nt], a0, a1, a2, a3, bf[k8][nt][0], bf[k8][nt][1]);
            }
        }
    }

    // direct epilogue: out[r][p] = x[r][p] + sA[r]*delta + d[r]
    float* ob = out + (size_t)b*C*HW;
    #pragma unroll
    for (int mt = 0; mt < 8; mt++) {
        const int r0 = mt*16 + gid, r1 = r0 + 8;
        const float d0 = dsm[r0], d1 = dsm[r1];
        const float a0 = asm_[r0], a1 = asm_[r1];
        #pragma unroll
        for (int nt = 0; nt < 2; nt++) {
            const int p = p0 + w*16 + nt*8 + 2*tig;
            float2 xv0 = *reinterpret_cast<const float2*>(xb + (size_t)r0*HW + p);
            float2 xv1 = *reinterpret_cast<const float2*>(xb + (size_t)r1*HW + p);
            float2 o0, o1;
            o0.x = fmaf(a0, acc[mt][nt][0], xv0.x + d0);
            o0.y = fmaf(a0, acc[mt][nt][1], xv0.y + d0);
            o1.x = fmaf(a1, acc[mt][nt][2], xv1.x + d1);
            o1.y = fmaf(a1, acc[mt][nt][3], xv1.y + d1);
            *reinterpret_cast<float2*>(ob + (size_t)r0*HW + p) = o0;
            *reinterpret_cast<float2*>(ob + (size_t)r1*HW + p) = o1;
        }
    }
}

extern "C" void kernel_launch(void* const* d_in, const int* in_sizes, int n_in,
                              void* d_out, int out_size) {
    const float* x     = (const float*)d_in[0];
    const float* Wsa   = (const float*)d_in[1];
    const float* bsa   = (const float*)d_in[2];
    const float* Wr    = (const float*)d_in[3];
    const float* br    = (const float*)d_in[4];
    const float* kn    = (const float*)d_in[5];
    const float* Wo    = (const float*)d_in[6];
    const float* bo    = (const float*)d_in[7];
    const float* alpha = (const float*)d_in[8];
    const float* sigma = (const float*)d_in[9];
    float* out = (float*)d_out;

    setup_kernel<<<(Bn*C*C + 255) / 256, 256>>>(Wsa, Wo, kn, out, out_size);
    gram_mma_kernel<<<dim3(KS, Bn), 256>>>(x);
    hgemm_kernel<<<dim3(6, Bn), 256>>>(Wr, Wsa, Wo);
    reduce_kernel<<<dim3(Bn, 16), 128>>>(Wr, Wsa, Wo, kn);
    finalize_kernel<<<Bn, 128>>>(bsa, br, kn, bo, alpha, sigma);
    out_mma_kernel<<<dim3(HW/128, Bn), 256>>>(x, out);
}